// round 10
// baseline (speedup 1.0000x reference)
#include <cuda_runtime.h>
#include <cuda_fp16.h>
#include <cstdint>

// ---------------- scratch (device globals: allocation-free) ----------------
__device__ __half g_pool2h[512 * 9216];         // conv2 out, NCHW flat, fp16
__device__ __half g_fc1w_h[128 * 9216];         // fc1 weights, fp16
__device__ float  g_fc1part[32 * 512 * 128];    // fc1 split-K partials

__device__ __forceinline__ uint32_t smem_u32(const void* p) {
    return (uint32_t)__cvta_generic_to_shared(p);
}
__device__ __forceinline__ uint64_t pack2(float lo, float hi) {
    uint64_t r;
    asm("mov.b64 %0, {%1, %2};" : "=l"(r) : "f"(lo), "f"(hi));
    return r;
}
__device__ __forceinline__ void fma2(uint64_t& d, uint64_t a, uint64_t b) {
    asm("fma.rn.f32x2 %0, %1, %2, %0;" : "+l"(d) : "l"(a), "l"(b));
}
__device__ __forceinline__ void unpack2(uint64_t v, float& lo, float& hi) {
    uint32_t l, h;
    asm("mov.b64 {%0, %1}, %2;" : "=r"(l), "=r"(h) : "l"(v));
    lo = __uint_as_float(l);
    hi = __uint_as_float(h);
}
__device__ __forceinline__ uint32_t cvt_f16x2(float hi, float lo) {
    uint32_t r;
    asm("cvt.rn.f16x2.f32 %0, %1, %2;" : "=r"(r) : "f"(hi), "f"(lo));
    return r;
}

// fp16 tensor-core MMA, fp32 accum (baseline PTX, sm_80+).
__device__ __forceinline__ void mma_f16(float c[4],
                                        uint32_t a0, uint32_t a1,
                                        uint32_t a2, uint32_t a3,
                                        uint32_t b0, uint32_t b1) {
    asm volatile(
        "mma.sync.aligned.m16n8k16.row.col.f32.f16.f16.f32 "
        "{%0,%1,%2,%3}, {%4,%5,%6,%7}, {%8,%9}, {%0,%1,%2,%3};"
        : "+f"(c[0]), "+f"(c[1]), "+f"(c[2]), "+f"(c[3])
        : "r"(a0), "r"(a1), "r"(a2), "r"(a3), "r"(b0), "r"(b1));
}
__device__ __forceinline__ void ldmx4(uint32_t r[4], uint32_t addr) {
    asm volatile(
        "ldmatrix.sync.aligned.m8n8.x4.shared.b16 {%0,%1,%2,%3}, [%4];"
        : "=r"(r[0]), "=r"(r[1]), "=r"(r[2]), "=r"(r[3]) : "r"(addr));
}
__device__ __forceinline__ void ldmx2(uint32_t& r0, uint32_t& r1, uint32_t addr) {
    asm volatile(
        "ldmatrix.sync.aligned.m8n8.x2.shared.b16 {%0,%1}, [%2];"
        : "=r"(r0), "=r"(r1) : "r"(addr));
}

// ============================================================================
// K0: one-time fc1 weight fp32 -> fp16.
// ============================================================================
__global__ void __launch_bounds__(512) cvt_w1(const float* __restrict__ w)
{
    const int i = (blockIdx.x * 512 + threadIdx.x);
    const float2 v = *(const float2*)(w + i * 2);
    *(uint32_t*)(g_fc1w_h + i * 2) = cvt_f16x2(v.y, v.x);
}

// ============================================================================
// K1 (fused): conv1+relu+pool -> conv2 (fp16 m16n8k16) -> bias+relu+pool.
// One CTA = HALF an image (12 conv-output rows), 1024 CTAs x 256 threads,
// 2 CTAs/SM resident: the two CTAs' serial phases overlap, hiding latency.
// GEMM view per CTA: M = 384 rows (14 input-grid rows x 26 + pad), N = 64 oc,
// K = 9 shifts x 32 ic. Warp w: 3 m16-tiles (mbase=w*48) x all 8 n8-tiles.
// A reads past row 364 land in s_b garbage -> only feed discarded outputs.
// Epilogue: fp16 [pix][66-padded oc] buffer; cvt commutes with max/relu so
// results are bit-identical to f32 pooling.
// ============================================================================
__global__ void __launch_bounds__(256, 2) convs_fused(
    const float* __restrict__ x,
    const float* __restrict__ w1,
    const float* __restrict__ b1,
    const float* __restrict__ w2,
    const float* __restrict__ b2)
{
    extern __shared__ char smc[];
    __half* s_a   = (__half*)smc;                 // 384 rows x 64B = 24576 B
    __half* s_b   = (__half*)(smc + 24576);       // 9*64 rows x 64B = 36864 B
    float*  s_img = (float*)(smc + 61440);        // 30*54 f32 = 6480 B
    __half* s_epi = (__half*)smc;                 // 288 pix x 66 (38016 B), reuse
    __shared__ uint64_t s_w1d[32 * 9];
    __shared__ float s_b1[32];
    __shared__ float s_bias[64];

    const int b    = blockIdx.x >> 1;
    const int half = blockIdx.x & 1;
    const int h0   = half * 12;         // conv-output row base
    const int tid  = threadIdx.x;
    const int wid  = tid >> 5;
    const int lane = tid & 31;
    const int g    = lane >> 2;
    const int tig  = lane & 3;

    // ---- phase 0: stage image slice + all weights + biases + pad ----
    {
        const float2* src = (const float2*)(x + b * 2916 + 2 * h0 * 54);
        float2* dst = (float2*)s_img;
        for (int i = tid; i < 810; i += 256) dst[i] = src[i];   // 30x54 f32
    }
    for (int i = tid; i < 32 * 9; i += 256) {
        const float wv = w1[i];
        s_w1d[i] = pack2(wv, wv);
    }
    if (tid < 32) s_b1[tid] = b1[tid];
    if (tid < 64) s_bias[tid] = b2[tid];
    for (int i = tid; i < 64 * 32 * 9; i += 256) {
        const int n = i / 288;
        const int r = i % 288;
        const int k = r / 9;
        const int s = r % 9;
        const int row = s * 64 + n;
        *(__half*)((char*)s_b + row * 64 +
            ((((k >> 3) ^ ((n >> 1) & 3)) << 4) | ((k & 7) << 1))) =
            __float2half_rn(w2[i]);
    }
    for (int i = 364 * 16 + tid; i < 384 * 16; i += 256)
        ((uint32_t*)s_a)[i] = 0u;       // zero A rows 364..383
    __syncthreads();

    // ---- phase 1: conv1 + relu + pool (f32x2 FMA) -> fp16 s_a rows ----
    for (int m = tid; m < 364; m += 256) {
        const int r  = m / 26;          // local input-grid row 0..13
        const int pw = m % 26;
        float in[4][4];
#pragma unroll
        for (int rr = 0; rr < 4; rr++)
#pragma unroll
            for (int c = 0; c < 4; c++)
                in[rr][c] = s_img[(2 * r + rr) * 54 + 2 * pw + c];
        uint64_t ap[4][3];
#pragma unroll
        for (int rr = 0; rr < 4; rr++)
#pragma unroll
            for (int j = 0; j < 3; j++)
                ap[rr][j] = pack2(in[rr][j], in[rr][j + 1]);

        char* arow = (char*)s_a + m * 64;
        const int sw2 = (m >> 1) & 3;
#pragma unroll 2
        for (int oc2 = 0; oc2 < 16; oc2++) {
            const int oca = oc2 * 2, ocb = oca + 1;
            uint64_t va0 = 0ull, va1 = 0ull, vb0 = 0ull, vb1 = 0ull;
#pragma unroll
            for (int t = 0; t < 9; t++) {
                const uint64_t wa = s_w1d[oca * 9 + t];
                const uint64_t wb = s_w1d[ocb * 9 + t];
                fma2(va0, ap[t / 3][t % 3], wa);
                fma2(va1, ap[t / 3 + 1][t % 3], wa);
                fma2(vb0, ap[t / 3][t % 3], wb);
                fma2(vb1, ap[t / 3 + 1][t % 3], wb);
            }
            float a00, a01, a10, a11, b00, b01, b10, b11;
            unpack2(va0, a00, a01); unpack2(va1, a10, a11);
            unpack2(vb0, b00, b01); unpack2(vb1, b10, b11);
            float ma = fmaxf(fmaxf(a00, a01), fmaxf(a10, a11)) + s_b1[oca];
            float mb = fmaxf(fmaxf(b00, b01), fmaxf(b10, b11)) + s_b1[ocb];
            ma = fmaxf(ma, 0.0f);
            mb = fmaxf(mb, 0.0f);
            *(uint32_t*)(arow +
                ((((oca >> 3) ^ sw2) << 4) | ((oca & 7) << 1))) =
                cvt_f16x2(mb, ma);
        }
    }
    __syncthreads();

    // ---- conv2 mainloop: warp = 3 m16-tiles x 8 n8-tiles ----
    float acc[3][8][4];
#pragma unroll
    for (int i = 0; i < 3; i++)
#pragma unroll
        for (int n = 0; n < 8; n++)
#pragma unroll
            for (int q = 0; q < 4; q++) acc[i][n][q] = 0.0f;

    const int mbase = wid * 48;

    const uint32_t a_base = smem_u32(s_a);
    const uint32_t b_base = smem_u32(s_b);
    const int lrow15 = lane & 15;
    const int lhi    = lane >> 4;
    const int bq     = (lane >> 3) & 1;            // B chunk select
    const int bsw    = ((lane & 7) >> 1) & 3;      // B swizzle (lane-const)
    const int brow_l = ((lane >> 4) & 1) * 8 + (lane & 7);  // row in 16-row pair

#pragma unroll 1
    for (int s = 0; s < 9; s++) {
        const int roff = (s / 3) * 26 + (s % 3);
        const int arow = mbase + roff + lrow15;
        const int asw  = (arow >> 1) & 3;
        const uint32_t a_row_addr = a_base + arow * 64;
        const uint32_t b_s_base   = b_base + (s * 64 + brow_l) * 64;

#pragma unroll
        for (int ks = 0; ks < 2; ks++) {
            const uint32_t aaddr =
                a_row_addr + ((uint32_t)((((ks << 1) + lhi) ^ asw)) << 4);
            const uint32_t bchunk =
                ((uint32_t)((((ks << 1) + bq) ^ bsw)) << 4);

            uint32_t bf[4][4];          // pair p -> n8-tiles 2p, 2p+1
#pragma unroll
            for (int p = 0; p < 4; p++)
                ldmx4(bf[p], b_s_base + p * 1024 + bchunk);

#pragma unroll
            for (int i = 0; i < 3; i++) {
                uint32_t a[4];
                ldmx4(a, aaddr + i * 1024);
#pragma unroll
                for (int nt = 0; nt < 8; nt++)
                    mma_f16(acc[i][nt], a[0], a[1], a[2], a[3],
                            bf[nt >> 1][(nt & 1) * 2],
                            bf[nt >> 1][(nt & 1) * 2 + 1]);
            }
        }
    }
    __syncthreads();   // results in regs; staging smem dead -> reuse as s_epi

    // ---- epilogue: bias + cvt -> fp16 [pix][66] smem ----
#pragma unroll
    for (int i = 0; i < 3; i++) {
        const int m0 = mbase + i * 16 + g;
        const int m1 = m0 + 8;
        const int r0 = m0 / 26, c0p = m0 % 26;
        const int r1 = m1 / 26, c1p = m1 % 26;
#pragma unroll
        for (int nt = 0; nt < 8; nt++) {
            const int col = nt * 8 + tig * 2;
            if (r0 < 12 && c0p < 24) {
                const int pix = r0 * 24 + c0p;
                *(uint32_t*)(s_epi + pix * 66 + col) =
                    cvt_f16x2(acc[i][nt][1] + s_bias[col + 1],
                              acc[i][nt][0] + s_bias[col]);
            }
            if (r1 < 12 && c1p < 24) {
                const int pix = r1 * 24 + c1p;
                *(uint32_t*)(s_epi + pix * 66 + col) =
                    cvt_f16x2(acc[i][nt][3] + s_bias[col + 1],
                              acc[i][nt][2] + s_bias[col]);
            }
        }
    }
    __syncthreads();

    // ---- 2x2 maxpool + relu -> fp16 NCHW flat (coalesced) ----
    __half* outp = g_pool2h + b * 9216 + half * 72;
    const __half2 z2 = __float2half2_rn(0.0f);
    for (int j = tid; j < 32 * 72; j += 256) {
        const int ocp = j / 72;         // oc pair
        const int p   = j % 72;         // pr*12+pw
        const int pr  = p / 12, pw = p % 12;
        const __half* e = s_epi + ((2 * pr) * 24 + 2 * pw) * 66 + ocp * 2;
        const __half2 v00 = *(const __half2*)(e);
        const __half2 v01 = *(const __half2*)(e + 66);
        const __half2 v10 = *(const __half2*)(e + 24 * 66);
        const __half2 v11 = *(const __half2*)(e + 25 * 66);
        const __half2 mx =
            __hmax2(__hmax2(__hmax2(v00, v01), __hmax2(v10, v11)), z2);
        outp[(ocp * 2) * 144 + p]     = __low2half(mx);
        outp[(ocp * 2 + 1) * 144 + p] = __high2half(mx);
    }
}

// ============================================================================
// K2: fc1 split-K (32 ways) via fp16 m16n8k16.  C[512,128] = A[512,9216]*W^T.
// ============================================================================
__global__ void __launch_bounds__(256) fc1_tc()
{
    __shared__ __half sA[64 * 32];
    __shared__ __half sB[128 * 32];

    const int mt   = blockIdx.x;    // 0..7
    const int ks   = blockIdx.y;    // 0..31
    const int tid  = threadIdx.x;
    const int wid  = tid >> 5;
    const int lane = tid & 31;
    const int m0   = mt * 64;
    const int k0   = ks * 288;
    const int mi   = wid & 3;
    const int nh   = wid >> 2;

    const int lrow15 = lane & 15;
    const int lhi    = lane >> 4;
    const int bch    = (lane >> 3) & 1;
    const int bsw    = ((lane & 7) >> 1) & 3;

    const uint32_t sA_base = smem_u32(sA);
    const uint32_t sB_base = smem_u32(sB);
    const int arow = mi * 16 + lrow15;
    const int asw  = (arow >> 1) & 3;
    const uint32_t a_row_addr = sA_base + arow * 64;
    const uint32_t b_row_addr = sB_base + (nh * 64 + (lane & 7)) * 64;

    float acc[8][4];
#pragma unroll
    for (int n = 0; n < 8; n++)
#pragma unroll
        for (int q = 0; q < 4; q++) acc[n][q] = 0.0f;

#pragma unroll 1
    for (int kk = 0; kk < 288; kk += 32) {
        __syncthreads();
        for (int i = tid; i < 64 * 16; i += 256) {
            const int m = i >> 4, k = (i & 15) * 2;
            const uint32_t v =
                *(const uint32_t*)(g_pool2h + (m0 + m) * 9216 + k0 + kk + k);
            *(uint32_t*)((char*)sA + m * 64 +
                ((((k >> 3) ^ ((m >> 1) & 3)) << 4) | ((k & 7) << 1))) = v;
        }
        for (int i = tid; i < 128 * 16; i += 256) {
            const int n = i >> 4, k = (i & 15) * 2;
            const uint32_t v =
                *(const uint32_t*)(g_fc1w_h + n * 9216 + k0 + kk + k);
            *(uint32_t*)((char*)sB + n * 64 +
                ((((k >> 3) ^ ((n >> 1) & 3)) << 4) | ((k & 7) << 1))) = v;
        }
        __syncthreads();

#pragma unroll
        for (int kstep = 0; kstep < 2; kstep++) {
            uint32_t a[4];
            ldmx4(a, a_row_addr +
                     ((uint32_t)((((kstep << 1) + lhi) ^ asw)) << 4));
            const uint32_t bk =
                b_row_addr + ((uint32_t)((((kstep << 1) + bch) ^ bsw)) << 4);
#pragma unroll
            for (int nt = 0; nt < 8; nt++) {
                uint32_t b0, b1;
                ldmx2(b0, b1, bk + nt * 512);
                mma_f16(acc[nt], a[0], a[1], a[2], a[3], b0, b1);
            }
        }
    }

    float* P = g_fc1part + (ks * 512 + m0) * 128;
    const int g   = lane >> 2;
    const int tig = lane & 3;
    const int r0  = mi * 16 + g;
#pragma unroll
    for (int n = 0; n < 8; n++) {
        const int c0 = nh * 64 + n * 8 + tig * 2;
        P[r0 * 128 + c0]           = acc[n][0];
        P[r0 * 128 + c0 + 1]       = acc[n][1];
        P[(r0 + 8) * 128 + c0]     = acc[n][2];
        P[(r0 + 8) * 128 + c0 + 1] = acc[n][3];
    }
}

// ============================================================================
// K3: reduce split-K partials + bias + relu + fc2.  4 images per block.
// ============================================================================
__global__ void __launch_bounds__(512) fc_tail(
    const float* __restrict__ b1,
    const float* __restrict__ w2,
    const float* __restrict__ b2,
    float* __restrict__ out)
{
    __shared__ float s_h[4][128];
    const int tid = threadIdx.x;
    const int sub = tid >> 7;           // image within block
    const int t   = tid & 127;
    const int b   = blockIdx.x * 4 + sub;

    float s = 0.f;
#pragma unroll
    for (int ks = 0; ks < 32; ks++)
        s += g_fc1part[(ks * 512 + b) * 128 + t];
    s_h[sub][t] = fmaxf(s + b1[t], 0.0f);
    __syncthreads();

    if (t < 10) {
        float acc = b2[t];
        const float* w = w2 + t * 128;
#pragma unroll 8
        for (int k = 0; k < 128; k++)
            acc = fmaf(s_h[sub][k], w[k], acc);
        out[b * 10 + t] = acc;
    }
}

// ============================================================================
extern "C" void kernel_launch(void* const* d_in, const int* in_sizes, int n_in,
                              void* d_out, int out_size)
{
    const float* x   = (const float*)d_in[0];
    const float* c1w = (const float*)d_in[1];
    const float* c1b = (const float*)d_in[2];
    const float* c2w = (const float*)d_in[3];
    const float* c2b = (const float*)d_in[4];
    const float* f1w = (const float*)d_in[5];
    const float* f1b = (const float*)d_in[6];
    const float* f2w = (const float*)d_in[7];
    const float* f2b = (const float*)d_in[8];
    float* out       = (float*)d_out;

    const int smem = 24576 + 36864 + 6480;   // 67920 B
    cudaFuncSetAttribute(convs_fused,
                         cudaFuncAttributeMaxDynamicSharedMemorySize, smem);

    cvt_w1<<<1152, 512>>>(f1w);
    convs_fused<<<1024, 256, smem>>>(x, c1w, c1b, c2w, c2b);

    dim3 g2(8, 32);
    fc1_tc<<<g2, 256>>>();

    fc_tail<<<128, 512>>>(f1b, f2w, f2b, out);
}

// round 11
// speedup vs baseline: 1.2782x; 1.2782x over previous
#include <cuda_runtime.h>
#include <cuda_fp16.h>
#include <cstdint>

// ---------------- scratch (device globals: allocation-free) ----------------
__device__ __half g_pool2h[512 * 9216];         // conv2 out, NCHW flat, fp16
__device__ __half g_fc1w_h[128 * 9216];         // fc1 weights, fp16
__device__ uint4  g_w2h[2304];                  // conv2 weights, pre-swizzled smem image (36864 B)
__device__ float  g_fc1part[32 * 512 * 128];    // fc1 split-K partials

__device__ __forceinline__ uint32_t smem_u32(const void* p) {
    return (uint32_t)__cvta_generic_to_shared(p);
}
__device__ __forceinline__ uint64_t pack2(float lo, float hi) {
    uint64_t r;
    asm("mov.b64 %0, {%1, %2};" : "=l"(r) : "f"(lo), "f"(hi));
    return r;
}
__device__ __forceinline__ void fma2(uint64_t& d, uint64_t a, uint64_t b) {
    asm("fma.rn.f32x2 %0, %1, %2, %0;" : "+l"(d) : "l"(a), "l"(b));
}
__device__ __forceinline__ void unpack2(uint64_t v, float& lo, float& hi) {
    uint32_t l, h;
    asm("mov.b64 {%0, %1}, %2;" : "=r"(l), "=r"(h) : "l"(v));
    lo = __uint_as_float(l);
    hi = __uint_as_float(h);
}
__device__ __forceinline__ uint32_t cvt_f16x2(float hi, float lo) {
    uint32_t r;
    asm("cvt.rn.f16x2.f32 %0, %1, %2;" : "=r"(r) : "f"(hi), "f"(lo));
    return r;
}

// fp16 tensor-core MMA, fp32 accum (baseline PTX, sm_80+).
__device__ __forceinline__ void mma_f16(float c[4],
                                        uint32_t a0, uint32_t a1,
                                        uint32_t a2, uint32_t a3,
                                        uint32_t b0, uint32_t b1) {
    asm volatile(
        "mma.sync.aligned.m16n8k16.row.col.f32.f16.f16.f32 "
        "{%0,%1,%2,%3}, {%4,%5,%6,%7}, {%8,%9}, {%0,%1,%2,%3};"
        : "+f"(c[0]), "+f"(c[1]), "+f"(c[2]), "+f"(c[3])
        : "r"(a0), "r"(a1), "r"(a2), "r"(a3), "r"(b0), "r"(b1));
}
__device__ __forceinline__ void ldmx4(uint32_t r[4], uint32_t addr) {
    asm volatile(
        "ldmatrix.sync.aligned.m8n8.x4.shared.b16 {%0,%1,%2,%3}, [%4];"
        : "=r"(r[0]), "=r"(r[1]), "=r"(r[2]), "=r"(r[3]) : "r"(addr));
}
__device__ __forceinline__ void ldmx2(uint32_t& r0, uint32_t& r1, uint32_t addr) {
    asm volatile(
        "ldmatrix.sync.aligned.m8n8.x2.shared.b16 {%0,%1}, [%2];"
        : "=r"(r0), "=r"(r1) : "r"(addr));
}

// ============================================================================
// K0a: one-time fc1 weight fp32 -> fp16.
// ============================================================================
__global__ void __launch_bounds__(512) cvt_w1(const float* __restrict__ w)
{
    const int i = (blockIdx.x * 512 + threadIdx.x);
    const float2 v = *(const float2*)(w + i * 2);
    *(uint32_t*)(g_fc1w_h + i * 2) = cvt_f16x2(v.y, v.x);
}

// ============================================================================
// K0b: one-time conv2 weight fp32 -> pre-swizzled fp16 smem image.
// Byte layout = exactly what convs_fused's s_b must contain.
// ============================================================================
__global__ void __launch_bounds__(512) cvt_w2(const float* __restrict__ w2)
{
    const int i = blockIdx.x * 512 + threadIdx.x;   // 18432 total
    const int n = i / 288;
    const int r = i % 288;
    const int k = r / 9;
    const int s = r % 9;
    const int row = s * 64 + n;
    *(__half*)((char*)g_w2h + row * 64 +
        ((((k >> 3) ^ ((n >> 1) & 3)) << 4) | ((k & 7) << 1))) =
        __float2half_rn(w2[i]);
}

// ============================================================================
// K1 (fused): conv1+relu+pool (f32x2 FMA) -> conv2 via fp16 m16n8k16 mma
//             -> bias+relu+pool -> NCHW fp16 gmem.
// One CTA = one image, 16 warps. conv2 GEMM: M = 640 pixel rows (26-grid),
// N = 64 oc, K = 9 shifts x 32 ic. Warp (mg,ng): 5 m16-tiles x 4 n8-tiles.
// s_b staged by raw uint4 copy from pre-swizzled g_w2h (no index ALU).
// Epilogue: fp16 [pix][66] buffer + __hmax2 pool (bit-identical to f32 pool).
// ============================================================================
__global__ void __launch_bounds__(512, 1) convs_fused(
    const float* __restrict__ x,
    const float* __restrict__ w1,
    const float* __restrict__ b1,
    const float* __restrict__ b2)
{
    extern __shared__ char smc[];
    __half* s_a   = (__half*)smc;                 // 704 rows x 64B = 45056 B
    __half* s_b   = (__half*)(smc + 45056);       // 9*64 rows x 64B = 36864 B
    float*  s_img = (float*)(smc + 81920);        // 54*54 f32 = 11664 B
    __half* s_epi = (__half*)smc;                 // 576 pix x 66 (76032 B), reuse
    __shared__ uint64_t s_w1d[32 * 9];
    __shared__ float s_b1[32];
    __shared__ float s_bias[64];

    const int b    = blockIdx.x;
    const int tid  = threadIdx.x;
    const int wid  = tid >> 5;
    const int lane = tid & 31;
    const int g    = lane >> 2;
    const int tig  = lane & 3;
    const int mg   = wid & 7;       // m-group: 5 m16-tiles
    const int ng   = wid >> 3;      // n-half: 4 n8-tiles

    // ---- phase 0: image + conv1 weights + biases + bulk weight copy ----
    {
        const float4* xb4 = (const float4*)(x + b * 54 * 54);
        float4* si4 = (float4*)s_img;
        for (int i = tid; i < 729; i += 512) si4[i] = xb4[i];
    }
    for (int i = tid; i < 32 * 9; i += 512) {
        const float wv = w1[i];
        s_w1d[i] = pack2(wv, wv);
    }
    if (tid < 32) s_b1[tid] = b1[tid];
    if (tid < 64) s_bias[tid] = b2[tid];
    {
        uint4* dst = (uint4*)s_b;
        for (int i = tid; i < 2304; i += 512) dst[i] = g_w2h[i];
    }
    for (int i = 676 * 16 + tid; i < 704 * 16; i += 512)
        ((uint32_t*)s_a)[i] = 0u;     // zero A rows 676..703
    __syncthreads();

    // ---- phase 1: conv1 + relu + pool -> fp16 swizzled s_a ----
    for (int m = tid; m < 676; m += 512) {
        const int ph = m / 26, pw = m % 26;
        float in[4][4];
#pragma unroll
        for (int r = 0; r < 4; r++)
#pragma unroll
            for (int c = 0; c < 4; c++)
                in[r][c] = s_img[(2 * ph + r) * 54 + 2 * pw + c];
        uint64_t ap[4][3];
#pragma unroll
        for (int r = 0; r < 4; r++)
#pragma unroll
            for (int j = 0; j < 3; j++)
                ap[r][j] = pack2(in[r][j], in[r][j + 1]);

        char* arow = (char*)s_a + m * 64;
        const int sw2 = (m >> 1) & 3;
#pragma unroll 2
        for (int oc2 = 0; oc2 < 16; oc2++) {
            const int oca = oc2 * 2, ocb = oca + 1;
            uint64_t va0 = 0ull, va1 = 0ull, vb0 = 0ull, vb1 = 0ull;
#pragma unroll
            for (int t = 0; t < 9; t++) {
                const uint64_t wa = s_w1d[oca * 9 + t];
                const uint64_t wb = s_w1d[ocb * 9 + t];
                fma2(va0, ap[t / 3][t % 3], wa);
                fma2(va1, ap[t / 3 + 1][t % 3], wa);
                fma2(vb0, ap[t / 3][t % 3], wb);
                fma2(vb1, ap[t / 3 + 1][t % 3], wb);
            }
            float a00, a01, a10, a11, b00, b01, b10, b11;
            unpack2(va0, a00, a01); unpack2(va1, a10, a11);
            unpack2(vb0, b00, b01); unpack2(vb1, b10, b11);
            float ma = fmaxf(fmaxf(a00, a01), fmaxf(a10, a11)) + s_b1[oca];
            float mb = fmaxf(fmaxf(b00, b01), fmaxf(b10, b11)) + s_b1[ocb];
            ma = fmaxf(ma, 0.0f);
            mb = fmaxf(mb, 0.0f);
            *(uint32_t*)(arow +
                ((((oca >> 3) ^ sw2) << 4) | ((oca & 7) << 1))) =
                cvt_f16x2(mb, ma);
        }
    }
    __syncthreads();

    // ---- conv2 mainloop: 9 shifts x 2 k16-steps, fp16 MMA ----
    float acc[5][4][4];
#pragma unroll
    for (int i = 0; i < 5; i++)
#pragma unroll
        for (int n = 0; n < 4; n++)
#pragma unroll
            for (int q = 0; q < 4; q++) acc[i][n][q] = 0.0f;

    const int mbase = mg * 80;

    const uint32_t a_base = smem_u32(s_a);
    const uint32_t b_base = smem_u32(s_b);
    const int lrow15 = lane & 15;
    const int lhi    = lane >> 4;
    const int bch    = (lane >> 3) & 1;
    const int bsw    = ((lane & 7) >> 1) & 3;
    const uint32_t b_lane_base = b_base + (ng * 32 + (lane & 7)) * 64;

#pragma unroll 1
    for (int s = 0; s < 9; s++) {
        const int roff = (s / 3) * 26 + (s % 3);
        const int arow = mbase + roff + lrow15;
        const int asw  = (arow >> 1) & 3;
        const uint32_t a_row_addr = a_base + arow * 64;
        const uint32_t b_row_addr = b_lane_base + s * 4096;

#pragma unroll
        for (int ks = 0; ks < 2; ks++) {
            const uint32_t aaddr =
                a_row_addr + ((uint32_t)((((ks << 1) + lhi) ^ asw)) << 4);
            const uint32_t bk =
                b_row_addr + ((uint32_t)((((ks << 1) + bch) ^ bsw)) << 4);

            uint32_t a[5][4];
#pragma unroll
            for (int i = 0; i < 5; i++) ldmx4(a[i], aaddr + i * 1024);

#pragma unroll
            for (int nt = 0; nt < 4; nt++) {
                uint32_t b0, b1;
                ldmx2(b0, b1, bk + nt * 512);
#pragma unroll
                for (int i = 0; i < 5; i++)
                    mma_f16(acc[i][nt], a[i][0], a[i][1], a[i][2], a[i][3], b0, b1);
            }
        }
    }
    __syncthreads();   // results in regs; staging smem dead -> reuse as s_epi

    // ---- epilogue: bias + cvt -> fp16 [pix][66] smem ----
#pragma unroll
    for (int i = 0; i < 5; i++) {
        const int m0 = mbase + i * 16 + g;
        const int m1 = m0 + 8;
        const int h0 = m0 / 26, w0 = m0 % 26;
        const int h1 = m1 / 26, w1 = m1 % 26;
#pragma unroll
        for (int nt = 0; nt < 4; nt++) {
            const int col = ng * 32 + nt * 8 + tig * 2;
            if (h0 < 24 && w0 < 24) {
                const int pix = h0 * 24 + w0;
                *(uint32_t*)(s_epi + pix * 66 + col) =
                    cvt_f16x2(acc[i][nt][1] + s_bias[col + 1],
                              acc[i][nt][0] + s_bias[col]);
            }
            if (h1 < 24 && w1 < 24) {
                const int pix = h1 * 24 + w1;
                *(uint32_t*)(s_epi + pix * 66 + col) =
                    cvt_f16x2(acc[i][nt][3] + s_bias[col + 1],
                              acc[i][nt][2] + s_bias[col]);
            }
        }
    }
    __syncthreads();

    // ---- 2x2 maxpool + relu (half2) -> fp16 NCHW flat (coalesced) ----
    __half* outp = g_pool2h + b * 9216;
    const __half2 z2 = __float2half2_rn(0.0f);
    for (int j = tid; j < 32 * 144; j += 512) {
        const int ocp = j / 144;        // oc pair
        const int p   = j % 144;
        const int pr  = p / 12, pw = p % 12;
        const __half* e = s_epi + ((2 * pr) * 24 + 2 * pw) * 66 + ocp * 2;
        const __half2 v00 = *(const __half2*)(e);
        const __half2 v01 = *(const __half2*)(e + 66);
        const __half2 v10 = *(const __half2*)(e + 24 * 66);
        const __half2 v11 = *(const __half2*)(e + 25 * 66);
        const __half2 mx =
            __hmax2(__hmax2(__hmax2(v00, v01), __hmax2(v10, v11)), z2);
        outp[(ocp * 2) * 144 + p]     = __low2half(mx);
        outp[(ocp * 2 + 1) * 144 + p] = __high2half(mx);
    }
}

// ============================================================================
// K2: fc1 split-K (32 ways) via fp16 m16n8k16, register double-buffered
// staging (prefetch chunk k+1 while computing chunk k).
// C[512,128] = A[512,9216] * W^T.  grid (8 mt, 32 ks), K=288/chunk.
// ============================================================================
__global__ void __launch_bounds__(256) fc1_tc()
{
    __shared__ __half sA[64 * 32];
    __shared__ __half sB[128 * 32];

    const int mt   = blockIdx.x;    // 0..7
    const int ks   = blockIdx.y;    // 0..31
    const int tid  = threadIdx.x;
    const int wid  = tid >> 5;
    const int lane = tid & 31;
    const int m0   = mt * 64;
    const int k0   = ks * 288;
    const int mi   = wid & 3;
    const int nh   = wid >> 2;

    // per-thread staging slots: A 4x, B 8x
    uint32_t sa_off[4], sb_off[8];
    const __half* agp[4];
    const __half* bgp[8];
#pragma unroll
    for (int j = 0; j < 4; j++) {
        const int i = tid + j * 256;
        const int m = i >> 4, k = (i & 15) * 2;
        sa_off[j] = m * 64 + ((((k >> 3) ^ ((m >> 1) & 3)) << 4) | ((k & 7) << 1));
        agp[j] = g_pool2h + (m0 + m) * 9216 + k0 + k;
    }
#pragma unroll
    for (int j = 0; j < 8; j++) {
        const int i = tid + j * 256;
        const int n = i >> 4, k = (i & 15) * 2;
        sb_off[j] = n * 64 + ((((k >> 3) ^ ((n >> 1) & 3)) << 4) | ((k & 7) << 1));
        bgp[j] = g_fc1w_h + n * 9216 + k0 + k;
    }

    const int lrow15 = lane & 15;
    const int lhi    = lane >> 4;
    const int bch    = (lane >> 3) & 1;
    const int bsw    = ((lane & 7) >> 1) & 3;

    const uint32_t sA_base = smem_u32(sA);
    const uint32_t sB_base = smem_u32(sB);
    const int arow = mi * 16 + lrow15;
    const int asw  = (arow >> 1) & 3;
    const uint32_t a_row_addr = sA_base + arow * 64;
    const uint32_t b_row_addr = sB_base + (nh * 64 + (lane & 7)) * 64;

    float acc[8][4];
#pragma unroll
    for (int n = 0; n < 8; n++)
#pragma unroll
        for (int q = 0; q < 4; q++) acc[n][q] = 0.0f;

    uint32_t ra[4], rb[8];
#pragma unroll
    for (int j = 0; j < 4; j++) ra[j] = *(const uint32_t*)(agp[j]);
#pragma unroll
    for (int j = 0; j < 8; j++) rb[j] = *(const uint32_t*)(bgp[j]);

#pragma unroll 1
    for (int kk = 0; kk < 288; kk += 32) {
#pragma unroll
        for (int j = 0; j < 4; j++)
            *(uint32_t*)((char*)sA + sa_off[j]) = ra[j];
#pragma unroll
        for (int j = 0; j < 8; j++)
            *(uint32_t*)((char*)sB + sb_off[j]) = rb[j];
        __syncthreads();

        if (kk + 32 < 288) {
#pragma unroll
            for (int j = 0; j < 4; j++) ra[j] = *(const uint32_t*)(agp[j] + kk + 32);
#pragma unroll
            for (int j = 0; j < 8; j++) rb[j] = *(const uint32_t*)(bgp[j] + kk + 32);
        }

#pragma unroll
        for (int kstep = 0; kstep < 2; kstep++) {
            uint32_t a[4];
            ldmx4(a, a_row_addr +
                     ((uint32_t)((((kstep << 1) + lhi) ^ asw)) << 4));
            const uint32_t bk =
                b_row_addr + ((uint32_t)((((kstep << 1) + bch) ^ bsw)) << 4);
#pragma unroll
            for (int nt = 0; nt < 8; nt++) {
                uint32_t b0, b1;
                ldmx2(b0, b1, bk + nt * 512);
                mma_f16(acc[nt], a[0], a[1], a[2], a[3], b0, b1);
            }
        }
        __syncthreads();
    }

    float* P = g_fc1part + (ks * 512 + m0) * 128;
    const int g   = lane >> 2;
    const int tig = lane & 3;
    const int r0  = mi * 16 + g;
#pragma unroll
    for (int n = 0; n < 8; n++) {
        const int c0 = nh * 64 + n * 8 + tig * 2;
        P[r0 * 128 + c0]           = acc[n][0];
        P[r0 * 128 + c0 + 1]       = acc[n][1];
        P[(r0 + 8) * 128 + c0]     = acc[n][2];
        P[(r0 + 8) * 128 + c0 + 1] = acc[n][3];
    }
}

// ============================================================================
// K3: reduce split-K partials + bias + relu + fc2 (128->10).
// ============================================================================
__global__ void __launch_bounds__(128) fc_tail(
    const float* __restrict__ b1,
    const float* __restrict__ w2,
    const float* __restrict__ b2,
    float* __restrict__ out)
{
    __shared__ float s_h[128];
    const int b   = blockIdx.x;
    const int tid = threadIdx.x;

    float s = 0.f;
#pragma unroll
    for (int ks = 0; ks < 32; ks++)
        s += g_fc1part[(ks * 512 + b) * 128 + tid];
    s_h[tid] = fmaxf(s + b1[tid], 0.0f);
    __syncthreads();

    if (tid < 10) {
        float acc = b2[tid];
        const float* w = w2 + tid * 128;
#pragma unroll 8
        for (int k = 0; k < 128; k++)
            acc = fmaf(s_h[k], w[k], acc);
        out[b * 10 + tid] = acc;
    }
}

// ============================================================================
extern "C" void kernel_launch(void* const* d_in, const int* in_sizes, int n_in,
                              void* d_out, int out_size)
{
    const float* x   = (const float*)d_in[0];
    const float* c1w = (const float*)d_in[1];
    const float* c1b = (const float*)d_in[2];
    const float* c2w = (const float*)d_in[3];
    const float* c2b = (const float*)d_in[4];
    const float* f1w = (const float*)d_in[5];
    const float* f1b = (const float*)d_in[6];
    const float* f2w = (const float*)d_in[7];
    const float* f2b = (const float*)d_in[8];
    float* out       = (float*)d_out;

    const int smem = 45056 + 36864 + 11664;   // 93584 B
    cudaFuncSetAttribute(convs_fused,
                         cudaFuncAttributeMaxDynamicSharedMemorySize, smem);

    cvt_w1<<<1152, 512>>>(f1w);
    cvt_w2<<<36, 512>>>(c2w);
    convs_fused<<<512, 512, smem>>>(x, c1w, c1b, c2b);

    dim3 g2(8, 32);
    fc1_tc<<<g2, 256>>>();

    fc_tail<<<512, 128>>>(f1b, f2w, f2b, out);
}

// round 13
// speedup vs baseline: 1.3520x; 1.0577x over previous
#include <cuda_runtime.h>
#include <cuda_fp16.h>
#include <cstdint>

// ---------------- scratch (device globals: allocation-free) ----------------
__device__ __half g_pool2h[512 * 9216];         // conv2 out, NCHW flat, fp16
__device__ __half g_fc1w_h[128 * 9216];         // fc1 weights, fp16
__device__ uint4  g_w2h[2304];                  // conv2 weights, pre-swizzled smem image
__device__ float  g_fc1part[32 * 512 * 128];    // fc1 split-K partials

__device__ __forceinline__ uint32_t smem_u32(const void* p) {
    return (uint32_t)__cvta_generic_to_shared(p);
}
__device__ __forceinline__ uint64_t pack2(float lo, float hi) {
    uint64_t r;
    asm("mov.b64 %0, {%1, %2};" : "=l"(r) : "f"(lo), "f"(hi));
    return r;
}
__device__ __forceinline__ void fma2(uint64_t& d, uint64_t a, uint64_t b) {
    asm("fma.rn.f32x2 %0, %1, %2, %0;" : "+l"(d) : "l"(a), "l"(b));
}
__device__ __forceinline__ void unpack2(uint64_t v, float& lo, float& hi) {
    uint32_t l, h;
    asm("mov.b64 {%0, %1}, %2;" : "=r"(l), "=r"(h) : "l"(v));
    lo = __uint_as_float(l);
    hi = __uint_as_float(h);
}
__device__ __forceinline__ uint32_t cvt_f16x2(float hi, float lo) {
    uint32_t r;
    asm("cvt.rn.f16x2.f32 %0, %1, %2;" : "=r"(r) : "f"(hi), "f"(lo));
    return r;
}

// fp16 tensor-core MMA, fp32 accum (baseline PTX, sm_80+).
__device__ __forceinline__ void mma_f16(float c[4],
                                        uint32_t a0, uint32_t a1,
                                        uint32_t a2, uint32_t a3,
                                        uint32_t b0, uint32_t b1) {
    asm volatile(
        "mma.sync.aligned.m16n8k16.row.col.f32.f16.f16.f32 "
        "{%0,%1,%2,%3}, {%4,%5,%6,%7}, {%8,%9}, {%0,%1,%2,%3};"
        : "+f"(c[0]), "+f"(c[1]), "+f"(c[2]), "+f"(c[3])
        : "r"(a0), "r"(a1), "r"(a2), "r"(a3), "r"(b0), "r"(b1));
}
__device__ __forceinline__ void ldmx4(uint32_t r[4], uint32_t addr) {
    asm volatile(
        "ldmatrix.sync.aligned.m8n8.x4.shared.b16 {%0,%1,%2,%3}, [%4];"
        : "=r"(r[0]), "=r"(r[1]), "=r"(r[2]), "=r"(r[3]) : "r"(addr));
}

// ============================================================================
// K0a: one-time fc1 weight fp32 -> fp16.
// ============================================================================
__global__ void __launch_bounds__(512) cvt_w1(const float* __restrict__ w)
{
    const int i = (blockIdx.x * 512 + threadIdx.x);
    const float2 v = *(const float2*)(w + i * 2);
    *(uint32_t*)(g_fc1w_h + i * 2) = cvt_f16x2(v.y, v.x);
}

// ============================================================================
// K0b: one-time conv2 weight fp32 -> pre-swizzled fp16 smem image.
// ============================================================================
__global__ void __launch_bounds__(512) cvt_w2(const float* __restrict__ w2)
{
    const int i = blockIdx.x * 512 + threadIdx.x;   // 18432 total
    const int n = i / 288;
    const int r = i % 288;
    const int k = r / 9;
    const int s = r % 9;
    const int row = s * 64 + n;
    *(__half*)((char*)g_w2h + row * 64 +
        ((((k >> 3) ^ ((n >> 1) & 3)) << 4) | ((k & 7) << 1))) =
        __float2half_rn(w2[i]);
}

// ============================================================================
// K1 (fused): conv1+relu+pool -> conv2 (fp16 m16n8k16) -> bias+relu+pool.
// One CTA = HALF an image (12 conv-output rows), 1024 CTAs x 256 threads,
// 2 CTAs/SM: the two resident CTAs' phases overlap (conv1 fma vs conv2 MMA).
// Weight staging = raw uint4 copy from pre-swizzled g_w2h.
// GEMM per CTA: M = 364 rows (14 grid rows x 26, pad to 384), N = 64 oc,
// K = 9 shifts x 32 ic. Warp w: 3 m16-tiles x 8 n8-tiles.
// ============================================================================
__global__ void __launch_bounds__(256, 2) convs_fused(
    const float* __restrict__ x,
    const float* __restrict__ w1,
    const float* __restrict__ b1,
    const float* __restrict__ b2)
{
    extern __shared__ char smc[];
    __half* s_a   = (__half*)smc;                 // 384 rows x 64B = 24576 B
    __half* s_b   = (__half*)(smc + 24576);       // 9*64 rows x 64B = 36864 B
    float*  s_img = (float*)(smc + 61440);        // 30*54 f32 = 6480 B
    __half* s_epi = (__half*)smc;                 // 288 pix x 66 (38016 B), reuse
    __shared__ uint64_t s_w1d[32 * 9];
    __shared__ float s_b1[32];
    __shared__ float s_bias[64];

    const int b    = blockIdx.x >> 1;
    const int half = blockIdx.x & 1;
    const int tid  = threadIdx.x;
    const int wid  = tid >> 5;
    const int lane = tid & 31;
    const int g    = lane >> 2;
    const int tig  = lane & 3;

    // ---- phase 0: image slice + conv1 weights + biases + bulk W copy ----
    {
        const float4* src = (const float4*)(x + b * 2916 + half * 24 * 54);
        float4* dst = (float4*)s_img;
        for (int i = tid; i < 405; i += 256) dst[i] = src[i];   // 30x54 f32
    }
    for (int i = tid; i < 32 * 9; i += 256) {
        const float wv = w1[i];
        s_w1d[i] = pack2(wv, wv);
    }
    if (tid < 32) s_b1[tid] = b1[tid];
    if (tid < 64) s_bias[tid] = b2[tid];
    {
        uint4* dst = (uint4*)s_b;
#pragma unroll
        for (int j = 0; j < 9; j++) dst[tid + j * 256] = g_w2h[tid + j * 256];
    }
    for (int i = 364 * 16 + tid; i < 384 * 16; i += 256)
        ((uint32_t*)s_a)[i] = 0u;       // zero A rows 364..383
    __syncthreads();

    // ---- phase 1: conv1 + relu + pool (f32x2 FMA) -> fp16 s_a rows ----
    for (int m = tid; m < 364; m += 256) {
        const int r  = m / 26;          // local grid row 0..13
        const int pw = m % 26;
        float in[4][4];
#pragma unroll
        for (int rr = 0; rr < 4; rr++)
#pragma unroll
            for (int c = 0; c < 4; c++)
                in[rr][c] = s_img[(2 * r + rr) * 54 + 2 * pw + c];
        uint64_t ap[4][3];
#pragma unroll
        for (int rr = 0; rr < 4; rr++)
#pragma unroll
            for (int j = 0; j < 3; j++)
                ap[rr][j] = pack2(in[rr][j], in[rr][j + 1]);

        char* arow = (char*)s_a + m * 64;
        const int sw2 = (m >> 1) & 3;
#pragma unroll 2
        for (int oc2 = 0; oc2 < 16; oc2++) {
            const int oca = oc2 * 2, ocb = oca + 1;
            uint64_t va0 = 0ull, va1 = 0ull, vb0 = 0ull, vb1 = 0ull;
#pragma unroll
            for (int t = 0; t < 9; t++) {
                const uint64_t wa = s_w1d[oca * 9 + t];
                const uint64_t wb = s_w1d[ocb * 9 + t];
                fma2(va0, ap[t / 3][t % 3], wa);
                fma2(va1, ap[t / 3 + 1][t % 3], wa);
                fma2(vb0, ap[t / 3][t % 3], wb);
                fma2(vb1, ap[t / 3 + 1][t % 3], wb);
            }
            float a00, a01, a10, a11, b00, b01, b10, b11;
            unpack2(va0, a00, a01); unpack2(va1, a10, a11);
            unpack2(vb0, b00, b01); unpack2(vb1, b10, b11);
            float ma = fmaxf(fmaxf(a00, a01), fmaxf(a10, a11)) + s_b1[oca];
            float mb = fmaxf(fmaxf(b00, b01), fmaxf(b10, b11)) + s_b1[ocb];
            ma = fmaxf(ma, 0.0f);
            mb = fmaxf(mb, 0.0f);
            *(uint32_t*)(arow +
                ((((oca >> 3) ^ sw2) << 4) | ((oca & 7) << 1))) =
                cvt_f16x2(mb, ma);
        }
    }
    __syncthreads();

    // ---- conv2 mainloop: warp = 3 m16-tiles x 8 n8-tiles ----
    float acc[3][8][4];
#pragma unroll
    for (int i = 0; i < 3; i++)
#pragma unroll
        for (int n = 0; n < 8; n++)
#pragma unroll
            for (int q = 0; q < 4; q++) acc[i][n][q] = 0.0f;

    const int mbase = wid * 48;

    const uint32_t a_base = smem_u32(s_a);
    const uint32_t b_base = smem_u32(s_b);
    const int lrow15 = lane & 15;
    const int lhi    = lane >> 4;
    const int bq     = (lane >> 3) & 1;
    const int bsw    = ((lane & 7) >> 1) & 3;
    const int brow_l = ((lane >> 4) & 1) * 8 + (lane & 7);

#pragma unroll 1
    for (int s = 0; s < 9; s++) {
        const int roff = (s / 3) * 26 + (s % 3);
        const int arow = mbase + roff + lrow15;
        const int asw  = (arow >> 1) & 3;
        const uint32_t a_row_addr = a_base + arow * 64;
        const uint32_t b_s_base   = b_base + (s * 64 + brow_l) * 64;

#pragma unroll
        for (int ks = 0; ks < 2; ks++) {
            const uint32_t aaddr =
                a_row_addr + ((uint32_t)((((ks << 1) + lhi) ^ asw)) << 4);
            const uint32_t bchunk =
                ((uint32_t)((((ks << 1) + bq) ^ bsw)) << 4);

            uint32_t bf[4][4];
#pragma unroll
            for (int p = 0; p < 4; p++)
                ldmx4(bf[p], b_s_base + p * 1024 + bchunk);

#pragma unroll
            for (int i = 0; i < 3; i++) {
                uint32_t a[4];
                ldmx4(a, aaddr + i * 1024);
#pragma unroll
                for (int nt = 0; nt < 8; nt++)
                    mma_f16(acc[i][nt], a[0], a[1], a[2], a[3],
                            bf[nt >> 1][(nt & 1) * 2],
                            bf[nt >> 1][(nt & 1) * 2 + 1]);
            }
        }
    }
    __syncthreads();   // results in regs; staging smem dead -> reuse as s_epi

    // ---- epilogue: bias + cvt -> fp16 [pix][66] smem ----
#pragma unroll
    for (int i = 0; i < 3; i++) {
        const int m0 = mbase + i * 16 + g;
        const int m1 = m0 + 8;
        const int r0 = m0 / 26, c0p = m0 % 26;
        const int r1 = m1 / 26, c1p = m1 % 26;
#pragma unroll
        for (int nt = 0; nt < 8; nt++) {
            const int col = nt * 8 + tig * 2;
            if (r0 < 12 && c0p < 24) {
                const int pix = r0 * 24 + c0p;
                *(uint32_t*)(s_epi + pix * 66 + col) =
                    cvt_f16x2(acc[i][nt][1] + s_bias[col + 1],
                              acc[i][nt][0] + s_bias[col]);
            }
            if (r1 < 12 && c1p < 24) {
                const int pix = r1 * 24 + c1p;
                *(uint32_t*)(s_epi + pix * 66 + col) =
                    cvt_f16x2(acc[i][nt][3] + s_bias[col + 1],
                              acc[i][nt][2] + s_bias[col]);
            }
        }
    }
    __syncthreads();

    // ---- 2x2 maxpool + relu (half2) -> fp16 NCHW flat (coalesced) ----
    __half* outp = g_pool2h + b * 9216 + half * 72;
    const __half2 z2 = __float2half2_rn(0.0f);
    for (int j = tid; j < 32 * 72; j += 256) {
        const int ocp = j / 72;
        const int p   = j % 72;
        const int pr  = p / 12, pw = p % 12;
        const __half* e = s_epi + ((2 * pr) * 24 + 2 * pw) * 66 + ocp * 2;
        const __half2 v00 = *(const __half2*)(e);
        const __half2 v01 = *(const __half2*)(e + 66);
        const __half2 v10 = *(const __half2*)(e + 24 * 66);
        const __half2 v11 = *(const __half2*)(e + 25 * 66);
        const __half2 mx =
            __hmax2(__hmax2(__hmax2(v00, v01), __hmax2(v10, v11)), z2);
        outp[(ocp * 2) * 144 + p]     = __low2half(mx);
        outp[(ocp * 2 + 1) * 144 + p] = __high2half(mx);
    }
}

// ============================================================================
// K2: fc1 split-K (32 ways) via fp16 m16n8k16, uint4 staging + register
// double buffering.  Slot counts FIXED: A = 256 uint4 chunks (1 slot),
// B = 512 uint4 chunks (2 slots).
// ============================================================================
__global__ void __launch_bounds__(256) fc1_tc()
{
    __shared__ __half sA[64 * 32];
    __shared__ __half sB[128 * 32];

    const int mt   = blockIdx.x;    // 0..7
    const int ks   = blockIdx.y;    // 0..31
    const int tid  = threadIdx.x;
    const int wid  = tid >> 5;
    const int lane = tid & 31;
    const int m0   = mt * 64;
    const int k0   = ks * 288;
    const int mi   = wid & 3;
    const int nh   = wid >> 2;

    // uint4 slots: A 1x (256 chunks = 64 rows x 4), B 2x (512 = 128 x 4).
    uint32_t sa_off, sb_off[2];
    const __half* agp;
    const __half* bgp[2];
    {
        const int m = tid >> 2, c = tid & 3;
        sa_off = m * 64 + ((c ^ ((m >> 1) & 3)) << 4);
        agp = g_pool2h + (m0 + m) * 9216 + k0 + c * 8;
    }
#pragma unroll
    for (int j = 0; j < 2; j++) {
        const int i = tid + j * 256;
        const int n = i >> 2, c = i & 3;
        sb_off[j] = n * 64 + ((c ^ ((n >> 1) & 3)) << 4);
        bgp[j] = g_fc1w_h + n * 9216 + k0 + c * 8;
    }

    const int lrow15 = lane & 15;
    const int lhi    = lane >> 4;
    const int bq     = (lane >> 3) & 1;
    const int bsw    = ((lane & 7) >> 1) & 3;
    const int brow_l = ((lane >> 4) & 1) * 8 + (lane & 7);

    const uint32_t sA_base = smem_u32(sA);
    const uint32_t sB_base = smem_u32(sB);
    const int arow = mi * 16 + lrow15;
    const int asw  = (arow >> 1) & 3;
    const uint32_t a_row_addr = sA_base + arow * 64;
    const uint32_t b_row_addr = sB_base + (nh * 64 + brow_l) * 64;

    float acc[8][4];
#pragma unroll
    for (int n = 0; n < 8; n++)
#pragma unroll
        for (int q = 0; q < 4; q++) acc[n][q] = 0.0f;

    uint4 ra, rb[2];
    ra = *(const uint4*)(agp);
#pragma unroll
    for (int j = 0; j < 2; j++) rb[j] = *(const uint4*)(bgp[j]);

#pragma unroll 1
    for (int kk = 0; kk < 288; kk += 32) {
        *(uint4*)((char*)sA + sa_off) = ra;
#pragma unroll
        for (int j = 0; j < 2; j++)
            *(uint4*)((char*)sB + sb_off[j]) = rb[j];
        __syncthreads();

        if (kk + 32 < 288) {
            ra = *(const uint4*)(agp + kk + 32);
#pragma unroll
            for (int j = 0; j < 2; j++)
                rb[j] = *(const uint4*)(bgp[j] + kk + 32);
        }

#pragma unroll
        for (int kstep = 0; kstep < 2; kstep++) {
            uint32_t a[4];
            ldmx4(a, a_row_addr +
                     ((uint32_t)((((kstep << 1) + lhi) ^ asw)) << 4));
            const uint32_t bchunk =
                ((uint32_t)((((kstep << 1) + bq) ^ bsw)) << 4);
            uint32_t bf[4][4];
#pragma unroll
            for (int p = 0; p < 4; p++)
                ldmx4(bf[p], b_row_addr + p * 1024 + bchunk);
#pragma unroll
            for (int nt = 0; nt < 8; nt++)
                mma_f16(acc[nt], a[0], a[1], a[2], a[3],
                        bf[nt >> 1][(nt & 1) * 2],
                        bf[nt >> 1][(nt & 1) * 2 + 1]);
        }
        __syncthreads();
    }

    float* P = g_fc1part + (ks * 512 + m0) * 128;
    const int g   = lane >> 2;
    const int tig = lane & 3;
    const int r0  = mi * 16 + g;
#pragma unroll
    for (int n = 0; n < 8; n++) {
        const int c0 = nh * 64 + n * 8 + tig * 2;
        P[r0 * 128 + c0]           = acc[n][0];
        P[r0 * 128 + c0 + 1]       = acc[n][1];
        P[(r0 + 8) * 128 + c0]     = acc[n][2];
        P[(r0 + 8) * 128 + c0 + 1] = acc[n][3];
    }
}

// ============================================================================
// K3: reduce split-K partials (2-way thread split) + bias + relu + fc2.
// ============================================================================
__global__ void __launch_bounds__(256) fc_tail(
    const float* __restrict__ b1,
    const float* __restrict__ w2,
    const float* __restrict__ b2,
    float* __restrict__ out)
{
    __shared__ float s_red[256];
    __shared__ float s_h[128];
    const int b    = blockIdx.x;
    const int tid  = threadIdx.x;
    const int t    = tid & 127;
    const int hseg = tid >> 7;

    float s = 0.f;
#pragma unroll
    for (int ks = hseg * 16; ks < hseg * 16 + 16; ks++)
        s += g_fc1part[(ks * 512 + b) * 128 + t];
    s_red[tid] = s;
    __syncthreads();

    if (tid < 128)
        s_h[tid] = fmaxf(s_red[tid] + s_red[tid + 128] + b1[tid], 0.0f);
    __syncthreads();

    if (tid < 10) {
        float acc = b2[tid];
        const float* w = w2 + tid * 128;
#pragma unroll 8
        for (int k = 0; k < 128; k++)
            acc = fmaf(s_h[k], w[k], acc);
        out[b * 10 + tid] = acc;
    }
}

// ============================================================================
extern "C" void kernel_launch(void* const* d_in, const int* in_sizes, int n_in,
                              void* d_out, int out_size)
{
    const float* x   = (const float*)d_in[0];
    const float* c1w = (const float*)d_in[1];
    const float* c1b = (const float*)d_in[2];
    const float* c2w = (const float*)d_in[3];
    const float* c2b = (const float*)d_in[4];
    const float* f1w = (const float*)d_in[5];
    const float* f1b = (const float*)d_in[6];
    const float* f2w = (const float*)d_in[7];
    const float* f2b = (const float*)d_in[8];
    float* out       = (float*)d_out;

    const int smem = 24576 + 36864 + 6480;   // 67920 B
    cudaFuncSetAttribute(convs_fused,
                         cudaFuncAttributeMaxDynamicSharedMemorySize, smem);

    cvt_w1<<<1152, 512>>>(f1w);
    cvt_w2<<<36, 512>>>(c2w);
    convs_fused<<<1024, 256, smem>>>(x, c1w, c1b, c2b);

    dim3 g2(8, 32);
    fc1_tc<<<g2, 256>>>();

    fc_tail<<<512, 256>>>(f1b, f2w, f2b, out);
}

// round 14
// speedup vs baseline: 1.4155x; 1.0470x over previous
#include <cuda_runtime.h>
#include <cuda_fp16.h>
#include <cstdint>

// ---------------- scratch (device globals: allocation-free) ----------------
__device__ __half g_pool2h[512 * 9216];         // conv2 out, NCHW flat, fp16
__device__ __half g_fc1w_h[128 * 9216];         // fc1 weights, fp16
__device__ uint4  g_w2h[2304];                  // conv2 weights, pre-swizzled smem image
__device__ float  g_fc1part[16 * 512 * 128];    // fc1 split-K partials

__device__ __forceinline__ uint32_t smem_u32(const void* p) {
    return (uint32_t)__cvta_generic_to_shared(p);
}
__device__ __forceinline__ uint64_t pack2(float lo, float hi) {
    uint64_t r;
    asm("mov.b64 %0, {%1, %2};" : "=l"(r) : "f"(lo), "f"(hi));
    return r;
}
__device__ __forceinline__ void fma2(uint64_t& d, uint64_t a, uint64_t b) {
    asm("fma.rn.f32x2 %0, %1, %2, %0;" : "+l"(d) : "l"(a), "l"(b));
}
__device__ __forceinline__ void unpack2(uint64_t v, float& lo, float& hi) {
    uint32_t l, h;
    asm("mov.b64 {%0, %1}, %2;" : "=r"(l), "=r"(h) : "l"(v));
    lo = __uint_as_float(l);
    hi = __uint_as_float(h);
}
__device__ __forceinline__ uint32_t cvt_f16x2(float hi, float lo) {
    uint32_t r;
    asm("cvt.rn.f16x2.f32 %0, %1, %2;" : "=r"(r) : "f"(hi), "f"(lo));
    return r;
}
__device__ __forceinline__ void cp16(uint32_t dst, const void* src) {
    asm volatile("cp.async.cg.shared.global [%0], [%1], 16;"
                 :: "r"(dst), "l"(src) : "memory");
}

// fp16 tensor-core MMA, fp32 accum (baseline PTX, sm_80+).
__device__ __forceinline__ void mma_f16(float c[4],
                                        uint32_t a0, uint32_t a1,
                                        uint32_t a2, uint32_t a3,
                                        uint32_t b0, uint32_t b1) {
    asm volatile(
        "mma.sync.aligned.m16n8k16.row.col.f32.f16.f16.f32 "
        "{%0,%1,%2,%3}, {%4,%5,%6,%7}, {%8,%9}, {%0,%1,%2,%3};"
        : "+f"(c[0]), "+f"(c[1]), "+f"(c[2]), "+f"(c[3])
        : "r"(a0), "r"(a1), "r"(a2), "r"(a3), "r"(b0), "r"(b1));
}
__device__ __forceinline__ void ldmx4(uint32_t r[4], uint32_t addr) {
    asm volatile(
        "ldmatrix.sync.aligned.m8n8.x4.shared.b16 {%0,%1,%2,%3}, [%4];"
        : "=r"(r[0]), "=r"(r[1]), "=r"(r[2]), "=r"(r[3]) : "r"(addr));
}

// ============================================================================
// K0: one-time weight conversions (fc1 -> fp16 flat; conv2 -> pre-swizzled).
// ============================================================================
__global__ void __launch_bounds__(512) cvt_weights(
    const float* __restrict__ w1fc,
    const float* __restrict__ w2conv)
{
    const int bid = blockIdx.x;
    if (bid < 1152) {
        const int i = bid * 512 + threadIdx.x;
        const float2 v = *(const float2*)(w1fc + i * 2);
        *(uint32_t*)(g_fc1w_h + i * 2) = cvt_f16x2(v.y, v.x);
    } else {
        const int i = (bid - 1152) * 512 + threadIdx.x;   // 18432 total
        const int n = i / 288;
        const int r = i % 288;
        const int k = r / 9;
        const int s = r % 9;
        const int row = s * 64 + n;
        *(__half*)((char*)g_w2h + row * 64 +
            ((((k >> 3) ^ ((n >> 1) & 3)) << 4) | ((k & 7) << 1))) =
            __float2half_rn(w2conv[i]);
    }
}

// ============================================================================
// K1 (fused): conv1+relu+pool -> conv2 (fp16 m16n8k16) -> bias+relu+pool.
// (unchanged from round 13 — 2-CTA/SM half-image version)
// ============================================================================
__global__ void __launch_bounds__(256, 2) convs_fused(
    const float* __restrict__ x,
    const float* __restrict__ w1,
    const float* __restrict__ b1,
    const float* __restrict__ b2)
{
    extern __shared__ char smc[];
    __half* s_a   = (__half*)smc;                 // 384 rows x 64B = 24576 B
    __half* s_b   = (__half*)(smc + 24576);       // 9*64 rows x 64B = 36864 B
    float*  s_img = (float*)(smc + 61440);        // 30*54 f32 = 6480 B
    __half* s_epi = (__half*)smc;                 // 288 pix x 66 (38016 B), reuse
    __shared__ uint64_t s_w1d[32 * 9];
    __shared__ float s_b1[32];
    __shared__ float s_bias[64];

    const int b    = blockIdx.x >> 1;
    const int half = blockIdx.x & 1;
    const int tid  = threadIdx.x;
    const int wid  = tid >> 5;
    const int lane = tid & 31;
    const int g    = lane >> 2;
    const int tig  = lane & 3;

    {
        const float4* src = (const float4*)(x + b * 2916 + half * 24 * 54);
        float4* dst = (float4*)s_img;
        for (int i = tid; i < 405; i += 256) dst[i] = src[i];
    }
    for (int i = tid; i < 32 * 9; i += 256) {
        const float wv = w1[i];
        s_w1d[i] = pack2(wv, wv);
    }
    if (tid < 32) s_b1[tid] = b1[tid];
    if (tid < 64) s_bias[tid] = b2[tid];
    {
        uint4* dst = (uint4*)s_b;
#pragma unroll
        for (int j = 0; j < 9; j++) dst[tid + j * 256] = g_w2h[tid + j * 256];
    }
    for (int i = 364 * 16 + tid; i < 384 * 16; i += 256)
        ((uint32_t*)s_a)[i] = 0u;
    __syncthreads();

    for (int m = tid; m < 364; m += 256) {
        const int r  = m / 26;
        const int pw = m % 26;
        float in[4][4];
#pragma unroll
        for (int rr = 0; rr < 4; rr++)
#pragma unroll
            for (int c = 0; c < 4; c++)
                in[rr][c] = s_img[(2 * r + rr) * 54 + 2 * pw + c];
        uint64_t ap[4][3];
#pragma unroll
        for (int rr = 0; rr < 4; rr++)
#pragma unroll
            for (int j = 0; j < 3; j++)
                ap[rr][j] = pack2(in[rr][j], in[rr][j + 1]);

        char* arow = (char*)s_a + m * 64;
        const int sw2 = (m >> 1) & 3;
#pragma unroll 2
        for (int oc2 = 0; oc2 < 16; oc2++) {
            const int oca = oc2 * 2, ocb = oca + 1;
            uint64_t va0 = 0ull, va1 = 0ull, vb0 = 0ull, vb1 = 0ull;
#pragma unroll
            for (int t = 0; t < 9; t++) {
                const uint64_t wa = s_w1d[oca * 9 + t];
                const uint64_t wb = s_w1d[ocb * 9 + t];
                fma2(va0, ap[t / 3][t % 3], wa);
                fma2(va1, ap[t / 3 + 1][t % 3], wa);
                fma2(vb0, ap[t / 3][t % 3], wb);
                fma2(vb1, ap[t / 3 + 1][t % 3], wb);
            }
            float a00, a01, a10, a11, b00, b01, b10, b11;
            unpack2(va0, a00, a01); unpack2(va1, a10, a11);
            unpack2(vb0, b00, b01); unpack2(vb1, b10, b11);
            float ma = fmaxf(fmaxf(a00, a01), fmaxf(a10, a11)) + s_b1[oca];
            float mb = fmaxf(fmaxf(b00, b01), fmaxf(b10, b11)) + s_b1[ocb];
            ma = fmaxf(ma, 0.0f);
            mb = fmaxf(mb, 0.0f);
            *(uint32_t*)(arow +
                ((((oca >> 3) ^ sw2) << 4) | ((oca & 7) << 1))) =
                cvt_f16x2(mb, ma);
        }
    }
    __syncthreads();

    float acc[3][8][4];
#pragma unroll
    for (int i = 0; i < 3; i++)
#pragma unroll
        for (int n = 0; n < 8; n++)
#pragma unroll
            for (int q = 0; q < 4; q++) acc[i][n][q] = 0.0f;

    const int mbase = wid * 48;

    const uint32_t a_base = smem_u32(s_a);
    const uint32_t b_base = smem_u32(s_b);
    const int lrow15 = lane & 15;
    const int lhi    = lane >> 4;
    const int bq     = (lane >> 3) & 1;
    const int bsw    = ((lane & 7) >> 1) & 3;
    const int brow_l = ((lane >> 4) & 1) * 8 + (lane & 7);

#pragma unroll 1
    for (int s = 0; s < 9; s++) {
        const int roff = (s / 3) * 26 + (s % 3);
        const int arow = mbase + roff + lrow15;
        const int asw  = (arow >> 1) & 3;
        const uint32_t a_row_addr = a_base + arow * 64;
        const uint32_t b_s_base   = b_base + (s * 64 + brow_l) * 64;

#pragma unroll
        for (int ks = 0; ks < 2; ks++) {
            const uint32_t aaddr =
                a_row_addr + ((uint32_t)((((ks << 1) + lhi) ^ asw)) << 4);
            const uint32_t bchunk =
                ((uint32_t)((((ks << 1) + bq) ^ bsw)) << 4);

            uint32_t bf[4][4];
#pragma unroll
            for (int p = 0; p < 4; p++)
                ldmx4(bf[p], b_s_base + p * 1024 + bchunk);

#pragma unroll
            for (int i = 0; i < 3; i++) {
                uint32_t a[4];
                ldmx4(a, aaddr + i * 1024);
#pragma unroll
                for (int nt = 0; nt < 8; nt++)
                    mma_f16(acc[i][nt], a[0], a[1], a[2], a[3],
                            bf[nt >> 1][(nt & 1) * 2],
                            bf[nt >> 1][(nt & 1) * 2 + 1]);
            }
        }
    }
    __syncthreads();

#pragma unroll
    for (int i = 0; i < 3; i++) {
        const int m0 = mbase + i * 16 + g;
        const int m1 = m0 + 8;
        const int r0 = m0 / 26, c0p = m0 % 26;
        const int r1 = m1 / 26, c1p = m1 % 26;
#pragma unroll
        for (int nt = 0; nt < 8; nt++) {
            const int col = nt * 8 + tig * 2;
            if (r0 < 12 && c0p < 24) {
                const int pix = r0 * 24 + c0p;
                *(uint32_t*)(s_epi + pix * 66 + col) =
                    cvt_f16x2(acc[i][nt][1] + s_bias[col + 1],
                              acc[i][nt][0] + s_bias[col]);
            }
            if (r1 < 12 && c1p < 24) {
                const int pix = r1 * 24 + c1p;
                *(uint32_t*)(s_epi + pix * 66 + col) =
                    cvt_f16x2(acc[i][nt][3] + s_bias[col + 1],
                              acc[i][nt][2] + s_bias[col]);
            }
        }
    }
    __syncthreads();

    __half* outp = g_pool2h + b * 9216 + half * 72;
    const __half2 z2 = __float2half2_rn(0.0f);
    for (int j = tid; j < 32 * 72; j += 256) {
        const int ocp = j / 72;
        const int p   = j % 72;
        const int pr  = p / 12, pw = p % 12;
        const __half* e = s_epi + ((2 * pr) * 24 + 2 * pw) * 66 + ocp * 2;
        const __half2 v00 = *(const __half2*)(e);
        const __half2 v01 = *(const __half2*)(e + 66);
        const __half2 v10 = *(const __half2*)(e + 24 * 66);
        const __half2 v11 = *(const __half2*)(e + 25 * 66);
        const __half2 mx =
            __hmax2(__hmax2(__hmax2(v00, v01), __hmax2(v10, v11)), z2);
        outp[(ocp * 2) * 144 + p]     = __low2half(mx);
        outp[(ocp * 2 + 1) * 144 + p] = __high2half(mx);
    }
}

// ============================================================================
// K2: fc1 split-K (16 ways) via fp16 m16n8k16 with cp.async 2-stage pipeline.
// grid (16 m-tiles of 32, 16 k-chunks of 576), 256 thr = 8 warps.
// Warp (mi = wid&1, nq = wid>>1): m16-tile x 32 cols (4 n8) -> 16 acc regs.
// Per 32-k sub-chunk: A = 128 uint4, B = 512 uint4, issued via cp.async.cg
// for sub-chunk c+1 while MMA consumes sub-chunk c.
// ============================================================================
__global__ void __launch_bounds__(256) fc1_tc()
{
    __shared__ __half sA[2][32 * 32];
    __shared__ __half sB[2][128 * 32];

    const int mt   = blockIdx.x;    // 0..15
    const int ks   = blockIdx.y;    // 0..15
    const int tid  = threadIdx.x;
    const int wid  = tid >> 5;
    const int lane = tid & 31;
    const int m0   = mt * 32;
    const int k0   = ks * 576;
    const int mi   = wid & 1;
    const int nq   = wid >> 1;      // 0..3

    // staging slots (uint4 granularity)
    uint32_t sa_off = 0;
    const __half* agp = nullptr;
    if (tid < 128) {
        const int m = tid >> 2, c = tid & 3;
        sa_off = m * 64 + ((c ^ ((m >> 1) & 3)) << 4);
        agp = g_pool2h + (m0 + m) * 9216 + k0 + c * 8;
    }
    uint32_t sb_off[2];
    const __half* bgp[2];
#pragma unroll
    for (int j = 0; j < 2; j++) {
        const int i = tid + j * 256;
        const int n = i >> 2, c = i & 3;
        sb_off[j] = n * 64 + ((c ^ ((n >> 1) & 3)) << 4);
        bgp[j] = g_fc1w_h + n * 9216 + k0 + c * 8;
    }

    const int lrow15 = lane & 15;
    const int lhi    = lane >> 4;
    const int bq     = (lane >> 3) & 1;
    const int bsw    = ((lane & 7) >> 1) & 3;
    const int brow_l = ((lane >> 4) & 1) * 8 + (lane & 7);

    const int arow = mi * 16 + lrow15;
    const int asw  = (arow >> 1) & 3;
    uint32_t aaddr_base[2], baddr_base[2];
#pragma unroll
    for (int buf = 0; buf < 2; buf++) {
        aaddr_base[buf] = smem_u32(sA[buf]) + arow * 64;
        baddr_base[buf] = smem_u32(sB[buf]) + (nq * 32 + brow_l) * 64;
    }

    float acc[4][4];
#pragma unroll
    for (int n = 0; n < 4; n++)
#pragma unroll
        for (int q = 0; q < 4; q++) acc[n][q] = 0.0f;

    // issue sub-chunk c into buffer buf
    auto issue = [&](int c, int buf) {
        const int koff = c * 32;
        if (tid < 128) cp16(smem_u32(sA[buf]) + sa_off, agp + koff);
        cp16(smem_u32(sB[buf]) + sb_off[0], bgp[0] + koff);
        cp16(smem_u32(sB[buf]) + sb_off[1], bgp[1] + koff);
        asm volatile("cp.async.commit_group;" ::: "memory");
    };

    issue(0, 0);

#pragma unroll 1
    for (int c = 0; c < 18; c++) {
        const int buf = c & 1;
        if (c + 1 < 18) {
            issue(c + 1, buf ^ 1);
            asm volatile("cp.async.wait_group 1;" ::: "memory");
        } else {
            asm volatile("cp.async.wait_group 0;" ::: "memory");
        }
        __syncthreads();

#pragma unroll
        for (int kstep = 0; kstep < 2; kstep++) {
            uint32_t a[4];
            ldmx4(a, aaddr_base[buf] +
                     ((uint32_t)((((kstep << 1) + lhi) ^ asw)) << 4));
            const uint32_t bchunk =
                ((uint32_t)((((kstep << 1) + bq) ^ bsw)) << 4);
            uint32_t bf[2][4];
#pragma unroll
            for (int p = 0; p < 2; p++)
                ldmx4(bf[p], baddr_base[buf] + p * 1024 + bchunk);
#pragma unroll
            for (int nt = 0; nt < 4; nt++)
                mma_f16(acc[nt], a[0], a[1], a[2], a[3],
                        bf[nt >> 1][(nt & 1) * 2],
                        bf[nt >> 1][(nt & 1) * 2 + 1]);
        }
        __syncthreads();
    }

    float* P = g_fc1part + (ks * 512 + m0) * 128;
    const int g   = lane >> 2;
    const int tig = lane & 3;
    const int r0  = mi * 16 + g;
#pragma unroll
    for (int n = 0; n < 4; n++) {
        const int c0 = nq * 32 + n * 8 + tig * 2;
        P[r0 * 128 + c0]           = acc[n][0];
        P[r0 * 128 + c0 + 1]       = acc[n][1];
        P[(r0 + 8) * 128 + c0]     = acc[n][2];
        P[(r0 + 8) * 128 + c0 + 1] = acc[n][3];
    }
}

// ============================================================================
// K3: reduce 16 split-K partials (2-way thread split) + bias + relu + fc2.
// ============================================================================
__global__ void __launch_bounds__(256) fc_tail(
    const float* __restrict__ b1,
    const float* __restrict__ w2,
    const float* __restrict__ b2,
    float* __restrict__ out)
{
    __shared__ float s_red[256];
    __shared__ float s_h[128];
    const int b    = blockIdx.x;
    const int tid  = threadIdx.x;
    const int t    = tid & 127;
    const int hseg = tid >> 7;

    float s = 0.f;
#pragma unroll
    for (int ks = hseg * 8; ks < hseg * 8 + 8; ks++)
        s += g_fc1part[(ks * 512 + b) * 128 + t];
    s_red[tid] = s;
    __syncthreads();

    if (tid < 128)
        s_h[tid] = fmaxf(s_red[tid] + s_red[tid + 128] + b1[tid], 0.0f);
    __syncthreads();

    if (tid < 10) {
        float acc = b2[tid];
        const float* w = w2 + tid * 128;
#pragma unroll 8
        for (int k = 0; k < 128; k++)
            acc = fmaf(s_h[k], w[k], acc);
        out[b * 10 + tid] = acc;
    }
}

// ============================================================================
extern "C" void kernel_launch(void* const* d_in, const int* in_sizes, int n_in,
                              void* d_out, int out_size)
{
    const float* x   = (const float*)d_in[0];
    const float* c1w = (const float*)d_in[1];
    const float* c1b = (const float*)d_in[2];
    const float* c2w = (const float*)d_in[3];
    const float* c2b = (const float*)d_in[4];
    const float* f1w = (const float*)d_in[5];
    const float* f1b = (const float*)d_in[6];
    const float* f2w = (const float*)d_in[7];
    const float* f2b = (const float*)d_in[8];
    float* out       = (float*)d_out;

    const int smem = 24576 + 36864 + 6480;   // 67920 B
    cudaFuncSetAttribute(convs_fused,
                         cudaFuncAttributeMaxDynamicSharedMemorySize, smem);

    cvt_weights<<<1188, 512>>>(f1w, c2w);
    convs_fused<<<1024, 256, smem>>>(x, c1w, c1b, c2b);

    dim3 g2(16, 16);
    fc1_tc<<<g2, 256>>>();

    fc_tail<<<512, 256>>>(f1b, f2w, f2b, out);
}